// round 5
// baseline (speedup 1.0000x reference)
#include <cuda_runtime.h>

typedef unsigned long long u64;

#define B_SZ   2048
#define T_LEN  256
#define E_DIM  50
#define H_DIM  50
#define G_DIM  200   // 4H
#define KP     52    // padded row (13 * float4 / 26 f32x2)
#define BPC    14    // batches per CTA
#define NT     288   // 9 warps: 200 gate threads, 24 idle, 64 dense
#define GRID   147   // ceil(2048/14)
#define ITEMS  (BPC * 50)   // 700 update/emb items

__device__ __forceinline__ u64 ffma2(u64 a, u64 b, u64 c) {
    u64 d; asm("fma.rn.f32x2 %0, %1, %2, %3;" : "=l"(d) : "l"(a), "l"(b), "l"(c));
    return d;
}
__device__ __forceinline__ u64 pack2(float lo, float hi) {
    u64 d; asm("mov.b64 %0, {%1, %2};" : "=l"(d) : "f"(lo), "f"(hi)); return d;
}
__device__ __forceinline__ float sum2(u64 v) {
    float lo, hi; asm("mov.b64 {%0, %1}, %2;" : "=f"(lo), "=f"(hi) : "l"(v));
    return lo + hi;
}
__device__ __forceinline__ float sigmoidf_(float x) {
    return __fdividef(1.f, 1.f + __expf(-x));
}
__device__ __forceinline__ float tanhf_(float x) {
    float ax = fabsf(x);
    float e  = __expf(-2.f * ax);
    return copysignf(__fdividef(1.f - e, 1.f + e), x);
}

// ---- gate weights: 2 columns (g0, g0+1) x 26 f32x2 pairs, named regs ----
#define LDWP(m) \
    const u64 wA##m = act ? pack2((2*(m)   < 50 ? wbase[(2*(m))  * G_DIM    ] : 0.f), \
                                  (2*(m)+1 < 50 ? wbase[(2*(m)+1)* G_DIM    ] : 0.f)) : 0ull; \
    const u64 wB##m = act ? pack2((2*(m)   < 50 ? wbase[(2*(m))  * G_DIM + 1] : 0.f), \
                                  (2*(m)+1 < 50 ? wbase[(2*(m)+1)* G_DIM + 1] : 0.f)) : 0ull;

#define GSTEP(i, ma, mb) { ulonglong2 q = sv[i]; \
    aA0 = ffma2(q.x, wA##ma, aA0); aA1 = ffma2(q.y, wA##mb, aA1); \
    aB0 = ffma2(q.x, wB##ma, aB0); aB1 = ffma2(q.y, wB##mb, aB1); }

// ---- dense weights: W1 column j, 26 f32x2 pairs ----
#define LDWD(m) \
    const u64 wd##m = dact ? pack2((2*(m)   < 50 ? W1[(2*(m))  * E_DIM + jj] : 0.f), \
                                   (2*(m)+1 < 50 ? W1[(2*(m)+1)* E_DIM + jj] : 0.f)) : 0ull;

#define DSTEP(i, ma, mb) { ulonglong2 q = sv[i]; \
    a0 = ffma2(q.x, wd##ma, a0); a1 = ffma2(q.y, wd##mb, a1); }

#define DPASS(SRCROW, DSTROW) { \
    const ulonglong2* sv = (const ulonglong2*)(SRCROW); \
    u64 a0 = pack2(b1j, 0.f), a1 = 0ull; \
    DSTEP(0,0,1)   DSTEP(1,2,3)   DSTEP(2,4,5)   DSTEP(3,6,7) \
    DSTEP(4,8,9)   DSTEP(5,10,11) DSTEP(6,12,13) DSTEP(7,14,15) \
    DSTEP(8,16,17) DSTEP(9,18,19) DSTEP(10,20,21) DSTEP(11,22,23) \
    DSTEP(12,24,25) \
    if (dact) (DSTROW)[jj] = fmaxf(sum2(a0) + sum2(a1), 0.f); }

// ---- update / prefetch item slots ----
#define ITEM_SETUP(r) \
    const int  u##r  = tid + (r) * NT; \
    const bool v##r  = (u##r < ITEMS); \
    const int  bl##r = v##r ? (u##r / 50) : 0; \
    const int  q##r  = v##r ? (u##r % 50) : 0; \
    const bool s##r  = v##r && (b0 + bl##r < B_SZ); \
    const int* ir##r = inp + (size_t)(s##r ? (b0 + bl##r) : 0) * T_LEN; \
    float cst##r = 0.f; float pre##r = 0.f;

#define PRELOAD(r) if (v##r) \
    xsh[0][bl##r][q##r] = s##r ? emb[(size_t)ir##r[0] * E_DIM + q##r] : 0.f;

#define PFETCH(r) { pre##r = 0.f; \
    if (s##r && pf) pre##r = emb[(size_t)ir##r[t + 1] * E_DIM + q##r]; }

#define UPDATE(r) if (doStep && v##r) { \
    float zi = zpart[0][bl##r][q##r]       + zpart[1][bl##r][q##r]; \
    float zf = zpart[0][bl##r][q##r +  50] + zpart[1][bl##r][q##r +  50]; \
    float zg = zpart[0][bl##r][q##r + 100] + zpart[1][bl##r][q##r + 100]; \
    float zo = zpart[0][bl##r][q##r + 150] + zpart[1][bl##r][q##r + 150]; \
    float ig = sigmoidf_(zi), fg = sigmoidf_(zf); \
    float gg = tanhf_(zg),    og = sigmoidf_(zo); \
    cst##r = fg * cst##r + ig * gg; \
    hsh[bl##r][q##r] = og * tanhf_(cst##r); \
    xsh[nxt][bl##r][q##r] = pre##r; }

__global__ void __launch_bounds__(NT, 1)
lstm_fused_all(const int* __restrict__ inp, const float* __restrict__ emb,
               const float* __restrict__ Wk, const float* __restrict__ Uk,
               const float* __restrict__ bias,
               const float* __restrict__ W1, const float* __restrict__ b1,
               const float* __restrict__ W2, const float* __restrict__ b2,
               float* __restrict__ out)
{
    __shared__ __align__(16) float xsh[2][BPC][KP];      // embedded inputs
    __shared__ __align__(16) float hsh[BPC][KP];         // hidden state
    __shared__ __align__(16) float zpart[2][BPC][G_DIM]; // gate partials
    __shared__ __align__(16) float d1b[2][BPC][KP];      // d1 (parity)
    __shared__ __align__(16) float d2b[2][BPC][KP];      // d2 (parity)
    __shared__ __align__(16) float w2s[KP];
    __shared__ float b2sh;

    const int tid = threadIdx.x;
    const int b0  = blockIdx.x * BPC;

    // Gate threads: tid < 200. role 0 = x@Wk, role 1 = h@Uk; 2 cols each.
    const bool act  = (tid < 200);
    const int  role = (tid >= 100) ? 1 : 0;
    const int  p    = act ? (tid % 100) : 0;
    const int  g0   = 2 * p;
    const float* wbase = (role ? Uk : Wk) + g0;
    LDWP(0)  LDWP(1)  LDWP(2)  LDWP(3)  LDWP(4)  LDWP(5)  LDWP(6)
    LDWP(7)  LDWP(8)  LDWP(9)  LDWP(10) LDWP(11) LDWP(12) LDWP(13)
    LDWP(14) LDWP(15) LDWP(16) LDWP(17) LDWP(18) LDWP(19) LDWP(20)
    LDWP(21) LDWP(22) LDWP(23) LDWP(24) LDWP(25)
    const float bgA = (act && role == 0) ? bias[g0]     : 0.f;
    const float bgB = (act && role == 0) ? bias[g0 + 1] : 0.f;

    // Dense threads: tid in [224, 288); j = tid-224 (active j < 50)
    const bool dense = (tid >= 224);
    const int  j     = tid - 224;
    const bool dact  = dense && (j < E_DIM);
    const int  jj    = dact ? j : 0;
    LDWD(0)  LDWD(1)  LDWD(2)  LDWD(3)  LDWD(4)  LDWD(5)  LDWD(6)
    LDWD(7)  LDWD(8)  LDWD(9)  LDWD(10) LDWD(11) LDWD(12) LDWD(13)
    LDWD(14) LDWD(15) LDWD(16) LDWD(17) LDWD(18) LDWD(19) LDWD(20)
    LDWD(21) LDWD(22) LDWD(23) LDWD(24) LDWD(25)
    const float b1j = dact ? b1[jj] : 0.f;

    // Zero padded shared rows (pads stay zero forever)
    for (int i = tid; i < BPC * KP; i += NT) {
        (&hsh[0][0])[i]      = 0.f;
        (&xsh[0][0][0])[i]   = 0.f;
        (&xsh[1][0][0])[i]   = 0.f;
        (&d1b[0][0][0])[i]   = 0.f;
        (&d1b[1][0][0])[i]   = 0.f;
        (&d2b[0][0][0])[i]   = 0.f;
        (&d2b[1][0][0])[i]   = 0.f;
    }
    for (int i = tid; i < KP; i += NT) w2s[i] = (i < E_DIM) ? W2[i] : 0.f;
    if (tid == 0) b2sh = b2[0];

    ITEM_SETUP(0) ITEM_SETUP(1) ITEM_SETUP(2)
    __syncthreads();
    PRELOAD(0) PRELOAD(1) PRELOAD(2)
    __syncthreads();

    // Pipelined loop: iter t does gates(t) || d1(t-1) || d2(t-2) || out(t-3)
    for (int t = 0; t < T_LEN + 3; t++) {
        const int  cur = t & 1, nxt = cur ^ 1;
        const bool pf     = (t + 1 < T_LEN);
        const bool doStep = (t < T_LEN);

        PFETCH(0) PFETCH(1) PFETCH(2)

        if (act) {
            if (doStep) {
                #pragma unroll 1
                for (int bl = 0; bl < BPC; bl++) {
                    const ulonglong2* sv =
                        (const ulonglong2*)(role ? hsh[bl] : xsh[cur][bl]);
                    u64 aA0 = pack2(bgA, 0.f), aA1 = 0ull;
                    u64 aB0 = pack2(bgB, 0.f), aB1 = 0ull;
                    GSTEP(0,0,1)   GSTEP(1,2,3)   GSTEP(2,4,5)   GSTEP(3,6,7)
                    GSTEP(4,8,9)   GSTEP(5,10,11) GSTEP(6,12,13) GSTEP(7,14,15)
                    GSTEP(8,16,17) GSTEP(9,18,19) GSTEP(10,20,21)
                    GSTEP(11,22,23) GSTEP(12,24,25)
                    float2 zz = make_float2(sum2(aA0) + sum2(aA1),
                                            sum2(aB0) + sum2(aB1));
                    *(float2*)&zpart[role][bl][g0] = zz;
                }
            }
        } else if (dense) {
            // d1(t-1) = relu(h(t-1) @ W1 + b1)
            if (t >= 1 && t <= T_LEN) {
                const int pw = (t - 1) & 1;
                #pragma unroll 1
                for (int bl = 0; bl < BPC; bl++) DPASS(hsh[bl], d1b[pw][bl]);
            }
            // d2(t-2) = relu(d1(t-2) @ W1 + b1)
            if (t >= 2 && t <= T_LEN + 1) {
                const int pw = (t - 2) & 1;
                #pragma unroll 1
                for (int bl = 0; bl < BPC; bl++) DPASS(d1b[pw][bl], d2b[pw][bl]);
            }
            // out(t-3) = sigmoid(d2(t-3) . W2 + b2)
            if (t >= 3 && j < BPC) {
                const int bgl = b0 + j;
                if (bgl < B_SZ) {
                    const float4* dv = (const float4*)d2b[(t - 3) & 1][j];
                    const float4* wv = (const float4*)w2s;
                    float r0 = b2sh, r1 = 0.f, r2 = 0.f, r3 = 0.f;
                    #pragma unroll
                    for (int pp = 0; pp < 13; pp++) {
                        float4 x = dv[pp], y = wv[pp];
                        r0 = fmaf(x.x, y.x, r0); r1 = fmaf(x.y, y.y, r1);
                        r2 = fmaf(x.z, y.z, r2); r3 = fmaf(x.w, y.w, r3);
                    }
                    out[(size_t)bgl * T_LEN + (t - 3)] = sigmoidf_((r0 + r1) + (r2 + r3));
                }
            }
        }
        __syncthreads();

        // State update (Keras order i,f,c,o) + commit prefetched x(t+1)
        UPDATE(0) UPDATE(1) UPDATE(2)
        __syncthreads();
    }
}

// ---------------------------------------------------------------------------
extern "C" void kernel_launch(void* const* d_in, const int* in_sizes, int n_in,
                              void* d_out, int out_size)
{
    const int*   inp = (const int*)  d_in[0];
    const float* emb = (const float*)d_in[1];
    const float* Wk  = (const float*)d_in[2];
    const float* Uk  = (const float*)d_in[3];
    const float* b   = (const float*)d_in[4];
    const float* W1  = (const float*)d_in[5];
    const float* b1  = (const float*)d_in[6];
    const float* W2  = (const float*)d_in[7];
    const float* b2  = (const float*)d_in[8];
    float* out = (float*)d_out;

    lstm_fused_all<<<GRID, NT>>>(inp, emb, Wk, Uk, b, W1, b1, W2, b2, out);
}

// round 6
// speedup vs baseline: 1.1007x; 1.1007x over previous
#include <cuda_runtime.h>

#define B_SZ   2048
#define T_LEN  256
#define E_DIM  50
#define H_DIM  50
#define G_DIM  200   // 4H
#define KP     52    // padded row (13 * float4)
#define BPC    14    // batches per CTA
#define NT     512   // 16 warps: 400 gate, 100 dense, 12 idle (phase1)
#define GRID   147   // ceil(2048/14)
#define ITEMS  (BPC * 50)   // 700 update/emb items

__device__ __forceinline__ float sigmoidf_(float x) {
    return __fdividef(1.f, 1.f + __expf(-x));
}
__device__ __forceinline__ float tanhf_(float x) {
    float ax = fabsf(x);
    float e  = __expf(-2.f * ax);
    return copysignf(__fdividef(1.f - e, 1.f + e), x);
}

// ---- gate weights: 50 named scalar registers (strided global load) ----
#define LDW(k) const float w##k = act ? wb[(k) * G_DIM] : 0.f;
#define GS(p, A, Bq, C, D) { float4 v = sv[p]; \
    a0 = fmaf(v.x, w##A,  a0); a1 = fmaf(v.y, w##Bq, a1); \
    a2 = fmaf(v.z, w##C,  a2); a3 = fmaf(v.w, w##D,  a3); }

// ---- dense weights: W1 column dj, 50 named scalar registers ----
#define LDWD(k) const float wd##k = dact ? W1[(k) * E_DIM + dj] : 0.f;
#define DGS(p, A, Bq, C, D) { float4 v = sv[p]; \
    a0 = fmaf(v.x, wd##A,  a0); a1 = fmaf(v.y, wd##Bq, a1); \
    a2 = fmaf(v.z, wd##C,  a2); a3 = fmaf(v.w, wd##D,  a3); }

// One dense row: DST = relu(b1j + dot(SRC, W1[:,dj]))  (SRC padded-52, pads 0)
#define DROW(SRC, DST) { \
    const float4* sv = (const float4*)(SRC); \
    float a0 = b1j, a1 = 0.f, a2 = 0.f, a3 = 0.f; \
    DGS(0,  0, 1, 2, 3)    DGS(1,  4, 5, 6, 7)    DGS(2,  8, 9, 10, 11) \
    DGS(3, 12, 13, 14, 15) DGS(4, 16, 17, 18, 19) DGS(5, 20, 21, 22, 23) \
    DGS(6, 24, 25, 26, 27) DGS(7, 28, 29, 30, 31) DGS(8, 32, 33, 34, 35) \
    DGS(9, 36, 37, 38, 39) DGS(10, 40, 41, 42, 43) DGS(11, 44, 45, 46, 47) \
    { float2 tv = *(const float2*)((const float*)sv + 48); \
      a0 = fmaf(tv.x, wd48, a0); a1 = fmaf(tv.y, wd49, a1); } \
    (DST) = fmaxf((a0 + a1) + (a2 + a3), 0.f); }

// ---- update / prefetch item slots ----
#define ITEM_SETUP(r) \
    const int  u##r  = tid + (r) * NT; \
    const bool v##r  = (u##r < ITEMS); \
    const int  bl##r = v##r ? (u##r / 50) : 0; \
    const int  q##r  = v##r ? (u##r % 50) : 0; \
    const bool s##r  = v##r && (b0 + bl##r < B_SZ); \
    const int* ir##r = inp + (size_t)(s##r ? (b0 + bl##r) : 0) * T_LEN; \
    float cst##r = 0.f; float pre##r = 0.f;

#define PRELOAD(r) if (v##r) \
    xsh[0][bl##r][q##r] = s##r ? emb[(size_t)ir##r[0] * E_DIM + q##r] : 0.f;

#define PFETCH(r) { pre##r = 0.f; \
    if (s##r && pf) pre##r = emb[(size_t)ir##r[t + 1] * E_DIM + q##r]; }

#define UPDATE(r) if (doStep && v##r) { \
    float zi = zpart[0][bl##r][q##r]       + zpart[1][bl##r][q##r]; \
    float zf = zpart[0][bl##r][q##r +  50] + zpart[1][bl##r][q##r +  50]; \
    float zg = zpart[0][bl##r][q##r + 100] + zpart[1][bl##r][q##r + 100]; \
    float zo = zpart[0][bl##r][q##r + 150] + zpart[1][bl##r][q##r + 150]; \
    float ig = sigmoidf_(zi), fg = sigmoidf_(zf); \
    float gg = tanhf_(zg),    og = sigmoidf_(zo); \
    cst##r = fg * cst##r + ig * gg; \
    hsh[bl##r][q##r] = og * tanhf_(cst##r); \
    xsh[nxt][bl##r][q##r] = pre##r; }

__global__ void __launch_bounds__(NT, 1)
lstm_fused_all(const int* __restrict__ inp, const float* __restrict__ emb,
               const float* __restrict__ Wk, const float* __restrict__ Uk,
               const float* __restrict__ bias,
               const float* __restrict__ W1, const float* __restrict__ b1,
               const float* __restrict__ W2, const float* __restrict__ b2,
               float* __restrict__ out)
{
    __shared__ __align__(16) float xsh[2][BPC][KP];      // embedded inputs
    __shared__ __align__(16) float hsh[BPC][KP];         // hidden state
    __shared__ __align__(16) float zpart[2][BPC][G_DIM]; // gate partials
    __shared__ __align__(16) float d1b[2][BPC][KP];      // d1 (parity by step)
    __shared__ __align__(16) float d2b[2][BPC][KP];      // d2 (parity by step)
    __shared__ __align__(16) float w2s[KP];

    const int tid = threadIdx.x;
    const int b0  = blockIdx.x * BPC;

    // ---- gate threads: tid < 400; role 0 = x@Wk, role 1 = h@Uk ----
    const bool act  = (tid < 2 * G_DIM);
    const int  role = (tid >= G_DIM) ? 1 : 0;
    const int  g    = act ? (tid % G_DIM) : 0;
    const float* wb = (role ? Uk : Wk) + g;
    LDW(0)  LDW(1)  LDW(2)  LDW(3)  LDW(4)  LDW(5)  LDW(6)  LDW(7)  LDW(8)  LDW(9)
    LDW(10) LDW(11) LDW(12) LDW(13) LDW(14) LDW(15) LDW(16) LDW(17) LDW(18) LDW(19)
    LDW(20) LDW(21) LDW(22) LDW(23) LDW(24) LDW(25) LDW(26) LDW(27) LDW(28) LDW(29)
    LDW(30) LDW(31) LDW(32) LDW(33) LDW(34) LDW(35) LDW(36) LDW(37) LDW(38) LDW(39)
    LDW(40) LDW(41) LDW(42) LDW(43) LDW(44) LDW(45) LDW(46) LDW(47) LDW(48) LDW(49)
    const float bg = (act && role == 0) ? bias[g] : 0.f;

    // ---- dense threads: tid in [400, 500); (column dj, batch-half dh) ----
    const bool dact = (tid >= 400) && (tid < 500);
    const int  dj   = dact ? ((tid - 400) % E_DIM) : 0;
    const int  dh   = dact ? ((tid - 400) / E_DIM) : 0;   // 0 or 1
    const int  blo  = dh * 7;                              // 7 batches per half
    LDWD(0)  LDWD(1)  LDWD(2)  LDWD(3)  LDWD(4)  LDWD(5)  LDWD(6)  LDWD(7)
    LDWD(8)  LDWD(9)  LDWD(10) LDWD(11) LDWD(12) LDWD(13) LDWD(14) LDWD(15)
    LDWD(16) LDWD(17) LDWD(18) LDWD(19) LDWD(20) LDWD(21) LDWD(22) LDWD(23)
    LDWD(24) LDWD(25) LDWD(26) LDWD(27) LDWD(28) LDWD(29) LDWD(30) LDWD(31)
    LDWD(32) LDWD(33) LDWD(34) LDWD(35) LDWD(36) LDWD(37) LDWD(38) LDWD(39)
    LDWD(40) LDWD(41) LDWD(42) LDWD(43) LDWD(44) LDWD(45) LDWD(46) LDWD(47)
    LDWD(48) LDWD(49)
    const float b1j = dact ? b1[dj] : 0.f;
    // out-writer threads: dense half 0, dj < BPC
    const bool oact = dact && (dh == 0) && (dj < BPC) && (b0 + dj < B_SZ);
    const float b2v = oact ? b2[0] : 0.f;

    // Zero padded shared rows (pads stay zero forever)
    for (int i = tid; i < BPC * KP; i += NT) {
        (&hsh[0][0])[i]    = 0.f;
        (&xsh[0][0][0])[i] = 0.f;
        (&xsh[1][0][0])[i] = 0.f;
        (&d1b[0][0][0])[i] = 0.f;
        (&d1b[1][0][0])[i] = 0.f;
        (&d2b[0][0][0])[i] = 0.f;
        (&d2b[1][0][0])[i] = 0.f;
    }
    for (int i = tid; i < KP; i += NT) w2s[i] = (i < E_DIM) ? W2[i] : 0.f;

    ITEM_SETUP(0) ITEM_SETUP(1)
    __syncthreads();
    PRELOAD(0) PRELOAD(1)
    __syncthreads();

    // Pipelined loop: iter t runs gates(t) || d1(t-1) || d2(t-2) || out(t-3)
    for (int t = 0; t < T_LEN + 3; t++) {
        const int  cur = t & 1, nxt = cur ^ 1;
        const bool pf     = (t + 1 < T_LEN);
        const bool doStep = (t < T_LEN);

        PFETCH(0) PFETCH(1)

        if (act) {
            // ---- gates(t): zpart[role][bl][g] ----
            if (doStep) {
                #pragma unroll 1
                for (int bl = 0; bl < BPC; bl++) {
                    const float4* sv = (const float4*)(role ? hsh[bl] : xsh[cur][bl]);
                    float a0 = bg, a1 = 0.f, a2 = 0.f, a3 = 0.f;
                    GS(0,  0, 1, 2, 3)    GS(1,  4, 5, 6, 7)    GS(2,  8, 9, 10, 11)
                    GS(3, 12, 13, 14, 15) GS(4, 16, 17, 18, 19) GS(5, 20, 21, 22, 23)
                    GS(6, 24, 25, 26, 27) GS(7, 28, 29, 30, 31) GS(8, 32, 33, 34, 35)
                    GS(9, 36, 37, 38, 39) GS(10, 40, 41, 42, 43) GS(11, 44, 45, 46, 47)
                    { float2 tv = *(const float2*)((const float*)sv + 48);
                      a0 = fmaf(tv.x, w48, a0); a1 = fmaf(tv.y, w49, a1); }
                    zpart[role][bl][g] = (a0 + a1) + (a2 + a3);
                }
            }
        } else if (dact) {
            // ---- out(t-3): sigmoid(d2(t-3) . W2 + b2) ----
            if (t >= 3 && oact) {
                const float4* sv = (const float4*)d2b[(t - 3) & 1][dj];
                const float4* wv = (const float4*)w2s;
                float r0 = b2v, r1 = 0.f, r2 = 0.f, r3 = 0.f;
                #pragma unroll
                for (int p = 0; p < 13; p++) {
                    float4 x = sv[p], y = wv[p];
                    r0 = fmaf(x.x, y.x, r0); r1 = fmaf(x.y, y.y, r1);
                    r2 = fmaf(x.z, y.z, r2); r3 = fmaf(x.w, y.w, r3);
                }
                out[(size_t)(b0 + dj) * T_LEN + (t - 3)] =
                    sigmoidf_((r0 + r1) + (r2 + r3));
            }
            // ---- d2(t-2) = relu(d1(t-2) @ W1 + b1) ----
            if (t >= 2 && t <= T_LEN + 1) {
                const int pw = (t - 2) & 1;
                #pragma unroll 1
                for (int bl = blo; bl < blo + 7; bl++)
                    DROW(d1b[pw][bl], d2b[pw][bl][dj]);
            }
            // ---- d1(t-1) = relu(h(t-1) @ W1 + b1) ----
            if (t >= 1 && t <= T_LEN) {
                const int pw = (t - 1) & 1;
                #pragma unroll 1
                for (int bl = blo; bl < blo + 7; bl++)
                    DROW(hsh[bl], d1b[pw][bl][dj]);
            }
        }
        __syncthreads();

        // ---- state update (Keras order i,f,c,o) + commit x(t+1) ----
        UPDATE(0) UPDATE(1)
        __syncthreads();
    }
}

// ---------------------------------------------------------------------------
extern "C" void kernel_launch(void* const* d_in, const int* in_sizes, int n_in,
                              void* d_out, int out_size)
{
    const int*   inp = (const int*)  d_in[0];
    const float* emb = (const float*)d_in[1];
    const float* Wk  = (const float*)d_in[2];
    const float* Uk  = (const float*)d_in[3];
    const float* b   = (const float*)d_in[4];
    const float* W1  = (const float*)d_in[5];
    const float* b1  = (const float*)d_in[6];
    const float* W2  = (const float*)d_in[7];
    const float* b2  = (const float*)d_in[8];
    float* out = (float*)d_out;

    lstm_fused_all<<<GRID, NT>>>(inp, emb, Wk, Uk, b, W1, b1, W2, b2, out);
}

// round 8
// speedup vs baseline: 1.1641x; 1.0576x over previous
#include <cuda_runtime.h>

typedef unsigned long long u64;

#define B_SZ   2048
#define T_LEN  256
#define E_DIM  50
#define H_DIM  50
#define G_DIM  200   // 4H
#define KP     52    // padded row (13 * float4 = 26 f32x2)
#define BPC    14    // batches per CTA
#define NT     512   // 16 warps: 400 gate, 100 dense, 12 aux
#define GRID   147   // ceil(2048/14)
#define ITEMS  (BPC * 50)   // 700 update/emb items

__device__ __forceinline__ u64 ffma2(u64 a, u64 b, u64 c) {
    u64 d; asm("fma.rn.f32x2 %0, %1, %2, %3;" : "=l"(d) : "l"(a), "l"(b), "l"(c));
    return d;
}
__device__ __forceinline__ u64 pack2(float lo, float hi) {
    u64 d; asm("mov.b64 %0, {%1, %2};" : "=l"(d) : "f"(lo), "f"(hi)); return d;
}
__device__ __forceinline__ float sum2(u64 v) {
    float lo, hi; asm("mov.b64 {%0, %1}, %2;" : "=f"(lo), "=f"(hi) : "l"(v));
    return lo + hi;
}
__device__ __forceinline__ float tanhapx(float x) {
    float y; asm("tanh.approx.f32 %0, %1;" : "=f"(y) : "f"(x)); return y;
}
__device__ __forceinline__ float sigapx(float x) {
    return fmaf(tanhapx(0.5f * x), 0.5f, 0.5f);
}

// ---- gate weights: 50 scalars as 25 packed u64 (strided global load) ----
#define LDWP(m) const u64 wp##m = act ? \
    pack2(wb[(2*(m)) * G_DIM], wb[(2*(m)+1) * G_DIM]) : 0ull;

// One ulonglong2 (4 floats) of both rows in a block-pair vs 2 weight pairs
#define GPP(i, m0, m1) { ulonglong2 qa = svA[i], qb = svB[i]; \
    aA0 = ffma2(qa.x, wp##m0, aA0); aA1 = ffma2(qa.y, wp##m1, aA1); \
    aB0 = ffma2(qb.x, wp##m0, aB0); aB1 = ffma2(qb.y, wp##m1, aB1); }

#define GATE_PAIR_BODY \
    GPP(0,0,1)   GPP(1,2,3)   GPP(2,4,5)   GPP(3,6,7)   GPP(4,8,9) \
    GPP(5,10,11) GPP(6,12,13) GPP(7,14,15) GPP(8,16,17) GPP(9,18,19) \
    GPP(10,20,21) GPP(11,22,23) GPP(12,24,25)

// ---- dense weights: W1 column dj, 50 scalars as 25 packed u64 ----
#define LDWD(m) const u64 wd##m = dact ? \
    pack2(W1[(2*(m)) * E_DIM + dj], W1[(2*(m)+1) * E_DIM + dj]) : 0ull;

#define DPP(i, m0, m1) { ulonglong2 q = sv[i]; \
    a0 = ffma2(q.x, wd##m0, a0); a1 = ffma2(q.y, wd##m1, a1); }

#define DROW(SRC, DST) { \
    const ulonglong2* sv = (const ulonglong2*)(SRC); \
    u64 a0 = pack2(b1j, 0.f), a1 = 0ull; \
    DPP(0,0,1)   DPP(1,2,3)   DPP(2,4,5)   DPP(3,6,7)   DPP(4,8,9) \
    DPP(5,10,11) DPP(6,12,13) DPP(7,14,15) DPP(8,16,17) DPP(9,18,19) \
    DPP(10,20,21) DPP(11,22,23) DPP(12,24,25) \
    (DST) = fmaxf(sum2(a0) + sum2(a1), 0.f); }

// ---- update / prefetch item slots ----
#define ITEM_SETUP(r) \
    const int  u##r  = tid + (r) * NT; \
    const bool v##r  = (u##r < ITEMS); \
    const int  bl##r = v##r ? (u##r / 50) : 0; \
    const int  q##r  = v##r ? (u##r % 50) : 0; \
    const bool s##r  = v##r && (b0 + bl##r < B_SZ); \
    const int* ir##r = inp + (size_t)(s##r ? (b0 + bl##r) : 0) * T_LEN; \
    float cst##r = 0.f; float pre##r = 0.f;

#define PRELOAD(r) if (v##r) \
    xsh[0][bl##r][q##r] = s##r ? emb[(size_t)ir##r[0] * E_DIM + q##r] : 0.f;

#define PFETCH(r) { pre##r = 0.f; \
    if (s##r && pf) pre##r = emb[(size_t)ir##r[t + 1] * E_DIM + q##r]; }

#define UPDATE(r) if (doStep && v##r) { \
    float zi = zpart[0][bl##r][q##r]       + zpart[1][bl##r][q##r]; \
    float zf = zpart[0][bl##r][q##r +  50] + zpart[1][bl##r][q##r +  50]; \
    float zg = zpart[0][bl##r][q##r + 100] + zpart[1][bl##r][q##r + 100]; \
    float zo = zpart[0][bl##r][q##r + 150] + zpart[1][bl##r][q##r + 150]; \
    float ig = sigapx(zi), fg = sigapx(zf); \
    float gg = tanhapx(zg), og = sigapx(zo); \
    cst##r = fg * cst##r + ig * gg; \
    hsh[bl##r][q##r] = og * tanhapx(cst##r); \
    xsh[nxt][bl##r][q##r] = pre##r; }

__global__ void __launch_bounds__(NT, 1)
lstm_fused_all(const int* __restrict__ inp, const float* __restrict__ emb,
               const float* __restrict__ Wk, const float* __restrict__ Uk,
               const float* __restrict__ bias,
               const float* __restrict__ W1, const float* __restrict__ b1,
               const float* __restrict__ W2, const float* __restrict__ b2,
               float* __restrict__ out)
{
    __shared__ __align__(16) float xsh[2][BPC][KP];      // embedded inputs
    __shared__ __align__(16) float hsh[BPC][KP];         // hidden state
    __shared__ __align__(16) float zpart[2][BPC][G_DIM]; // gate partials
    __shared__ __align__(16) float d1b[2][BPC][KP];      // d1 (parity by step)
    __shared__ __align__(16) float d2b[2][BPC][KP];      // d2 (parity by step)
    __shared__ __align__(16) float w2s[KP];

    const int tid = threadIdx.x;
    const int b0  = blockIdx.x * BPC;

    // ---- gate threads: tid < 400; role 0 = x@Wk, role 1 = h@Uk ----
    const bool act  = (tid < 2 * G_DIM);
    const int  role = (tid >= G_DIM) ? 1 : 0;
    const int  g    = act ? (tid % G_DIM) : 0;
    const float* wb = (role ? Uk : Wk) + g;
    LDWP(0)  LDWP(1)  LDWP(2)  LDWP(3)  LDWP(4)  LDWP(5)  LDWP(6)
    LDWP(7)  LDWP(8)  LDWP(9)  LDWP(10) LDWP(11) LDWP(12) LDWP(13)
    LDWP(14) LDWP(15) LDWP(16) LDWP(17) LDWP(18) LDWP(19) LDWP(20)
    LDWP(21) LDWP(22) LDWP(23) LDWP(24)
    const u64 wp25 = 0ull;   // multiplies the zero pad (floats 50,51)
    const float bg = (act && role == 0) ? bias[g] : 0.f;

    // ---- dense threads: tid in [400, 500); (column dj, batch-half dh) ----
    const bool dact = (tid >= 400) && (tid < 500);
    const int  dj   = dact ? ((tid - 400) % E_DIM) : 0;
    const int  dh   = dact ? ((tid - 400) / E_DIM) : 0;   // 0 or 1
    const int  blo  = dh * 7;                              // 7 batches per half
    LDWD(0)  LDWD(1)  LDWD(2)  LDWD(3)  LDWD(4)  LDWD(5)  LDWD(6)
    LDWD(7)  LDWD(8)  LDWD(9)  LDWD(10) LDWD(11) LDWD(12) LDWD(13)
    LDWD(14) LDWD(15) LDWD(16) LDWD(17) LDWD(18) LDWD(19) LDWD(20)
    LDWD(21) LDWD(22) LDWD(23) LDWD(24)
    const u64 wd25 = 0ull;   // multiplies the zero pad (floats 50,51)
    const float b1j = dact ? b1[dj] : 0.f;
    // out-writer threads: dense half 0, dj < BPC
    const bool oact = dact && (dh == 0) && (dj < BPC) && (b0 + dj < B_SZ);
    const float b2v = oact ? b2[0] : 0.f;

    // Zero padded shared rows (pads stay zero forever)
    for (int i = tid; i < BPC * KP; i += NT) {
        (&hsh[0][0])[i]    = 0.f;
        (&xsh[0][0][0])[i] = 0.f;
        (&xsh[1][0][0])[i] = 0.f;
        (&d1b[0][0][0])[i] = 0.f;
        (&d1b[1][0][0])[i] = 0.f;
        (&d2b[0][0][0])[i] = 0.f;
        (&d2b[1][0][0])[i] = 0.f;
    }
    for (int i = tid; i < KP; i += NT) w2s[i] = (i < E_DIM) ? W2[i] : 0.f;

    ITEM_SETUP(0) ITEM_SETUP(1)
    __syncthreads();
    PRELOAD(0) PRELOAD(1)
    __syncthreads();

    // Pipelined loop: iter t runs gates(t) || d1(t-1) || d2(t-2) || out(t-3)
    for (int t = 0; t < T_LEN + 3; t++) {
        const int  cur = t & 1, nxt = cur ^ 1;
        const bool pf     = (t + 1 < T_LEN);
        const bool doStep = (t < T_LEN);

        PFETCH(0) PFETCH(1)

        if (act) {
            // ---- gates(t): block pairs for doubled ILP ----
            if (doStep) {
                #pragma unroll 1
                for (int blp = 0; blp < BPC; blp += 2) {
                    const ulonglong2* svA = (const ulonglong2*)
                        (role ? hsh[blp]     : xsh[cur][blp]);
                    const ulonglong2* svB = (const ulonglong2*)
                        (role ? hsh[blp + 1] : xsh[cur][blp + 1]);
                    u64 aA0 = pack2(bg, 0.f), aA1 = 0ull;
                    u64 aB0 = pack2(bg, 0.f), aB1 = 0ull;
                    GATE_PAIR_BODY
                    zpart[role][blp][g]     = sum2(aA0) + sum2(aA1);
                    zpart[role][blp + 1][g] = sum2(aB0) + sum2(aB1);
                }
            }
        } else if (dact) {
            // ---- out(t-3): sigmoid(d2(t-3) . W2 + b2) ----
            if (t >= 3 && oact) {
                const float4* sv = (const float4*)d2b[(t - 3) & 1][dj];
                const float4* wv = (const float4*)w2s;
                float r0 = b2v, r1 = 0.f, r2 = 0.f, r3 = 0.f;
                #pragma unroll
                for (int p = 0; p < 13; p++) {
                    float4 x = sv[p], y = wv[p];
                    r0 = fmaf(x.x, y.x, r0); r1 = fmaf(x.y, y.y, r1);
                    r2 = fmaf(x.z, y.z, r2); r3 = fmaf(x.w, y.w, r3);
                }
                out[(size_t)(b0 + dj) * T_LEN + (t - 3)] =
                    sigapx((r0 + r1) + (r2 + r3));
            }
            // ---- d2(t-2) = relu(d1(t-2) @ W1 + b1) ----
            if (t >= 2 && t <= T_LEN + 1) {
                const int pw = (t - 2) & 1;
                #pragma unroll 1
                for (int bl = blo; bl < blo + 7; bl++)
                    DROW(d1b[pw][bl], d2b[pw][bl][dj]);
            }
            // ---- d1(t-1) = relu(h(t-1) @ W1 + b1) ----
            if (t >= 1 && t <= T_LEN) {
                const int pw = (t - 1) & 1;
                #pragma unroll 1
                for (int bl = blo; bl < blo + 7; bl++)
                    DROW(hsh[bl], d1b[pw][bl][dj]);
            }
        }
        __syncthreads();

        // ---- state update (Keras order i,f,c,o) + commit x(t+1) ----
        UPDATE(0) UPDATE(1)
        __syncthreads();
    }
}

// ---------------------------------------------------------------------------
extern "C" void kernel_launch(void* const* d_in, const int* in_sizes, int n_in,
                              void* d_out, int out_size)
{
    const int*   inp = (const int*)  d_in[0];
    const float* emb = (const float*)d_in[1];
    const float* Wk  = (const float*)d_in[2];
    const float* Uk  = (const float*)d_in[3];
    const float* b   = (const float*)d_in[4];
    const float* W1  = (const float*)d_in[5];
    const float* b1  = (const float*)d_in[6];
    const float* W2  = (const float*)d_in[7];
    const float* b2  = (const float*)d_in[8];
    float* out = (float*)d_out;

    lstm_fused_all<<<GRID, NT>>>(inp, emb, Wk, Uk, b, W1, b1, W2, b2, out);
}